// round 5
// baseline (speedup 1.0000x reference)
#include <cuda_runtime.h>
#include <cstdint>

#define N_NODES 100000
#define F_IN 256
#define N_HID 128
#define N_CLS 40

// ---------------- device scratch (static, no allocations) ----------------
__device__ float g_norm_src[N_NODES];
__device__ float g_norm_dst[N_NODES];
__device__ float g_h[(size_t)N_NODES * N_HID];    // layer-1 projected features
__device__ float g_agg[(size_t)N_NODES * N_HID];  // layer-1 aggregation
__device__ float g_h2[(size_t)N_NODES * N_CLS];   // layer-2 projected features
__device__ uint32_t g_w1t[(size_t)N_HID * F_IN];  // W1^T [n][k], tf32-rounded bits
__device__ int   g_idx64;                          // 1 if src/dst are int64

// ---------------- helpers ----------------
__device__ __forceinline__ int load_idx(const int* p, int e) {
    return g_idx64 ? p[2 * e] : p[e];
}

__device__ __forceinline__ uint32_t cvt_tf32(float f) {
    uint32_t u;
    asm("cvt.rna.tf32.f32 %0, %1;" : "=r"(u) : "f"(f));
    return u;
}

__device__ __forceinline__ void mma_tf32(float* c, const uint32_t* a, const uint32_t* b) {
    asm volatile("mma.sync.aligned.m16n8k8.row.col.f32.tf32.tf32.f32 "
        "{%0,%1,%2,%3}, {%4,%5,%6,%7}, {%8,%9}, {%0,%1,%2,%3};"
        : "+f"(c[0]), "+f"(c[1]), "+f"(c[2]), "+f"(c[3])
        : "r"(a[0]), "r"(a[1]), "r"(a[2]), "r"(a[3]), "r"(b[0]), "r"(b[1]));
}

// ---------------- init ----------------
__global__ void init_kernel(float4* __restrict__ out4, const int* __restrict__ src32,
                            int n, int nOut4) {
    long long i = (long long)blockIdx.x * blockDim.x + threadIdx.x;
    long long stride = (long long)gridDim.x * blockDim.x;
    float4 z = make_float4(0.f, 0.f, 0.f, 0.f);

    if (i == 0) {
        int is64 = 1;
        #pragma unroll 1
        for (int k = 0; k < 64; k++) {
            if (src32[2 * k + 1] != 0) { is64 = 0; break; }
        }
        g_idx64 = is64;
    }

    long long nAgg4 = (long long)n * N_HID / 4;
    float4* agg4 = (float4*)g_agg;
    for (long long j = i; j < nAgg4; j += stride) agg4[j] = z;
    for (long long j = i; j < nOut4; j += stride) out4[j] = z;

    long long nN4 = n / 4;
    float4* ns4 = (float4*)g_norm_src;
    float4* nd4 = (float4*)g_norm_dst;
    for (long long j = i; j < nN4; j += stride) { ns4[j] = z; nd4[j] = z; }
    for (long long j = nN4 * 4 + i; j < n; j += stride) { g_norm_src[j] = 0.f; g_norm_dst[j] = 0.f; }
}

// ---------------- degrees ----------------
__global__ void degree_kernel(const int* __restrict__ src, const int* __restrict__ dst, int E) {
    int i = blockIdx.x * blockDim.x + threadIdx.x;
    if (i < E) {
        atomicAdd(&g_norm_src[load_idx(src, i)], 1.0f);
        atomicAdd(&g_norm_dst[load_idx(dst, i)], 1.0f);
    }
}

__global__ void norm_kernel(int n) {
    int i = blockIdx.x * blockDim.x + threadIdx.x;
    if (i < n) {
        float a = g_norm_src[i];
        g_norm_src[i] = (a > 0.f) ? rsqrtf(a) : 0.f;
        float b = g_norm_dst[i];
        g_norm_dst[i] = (b > 0.f) ? rsqrtf(b) : 0.f;
    }
}

// ---------------- W1 transpose + tf32 rounding: g_w1t[n][k] = tf32(W1[k][n]) ----------------
__global__ void w1t_kernel(const float* __restrict__ W1) {
    int i = blockIdx.x * blockDim.x + threadIdx.x;
    if (i < N_HID * F_IN) {
        int nrow = i >> 8;          // 0..127
        int k = i & 255;            // 0..255
        g_w1t[(size_t)nrow * F_IN + k] = cvt_tf32(W1[(size_t)k * N_HID + nrow]);
    }
}

// ---------------- GEMM1 (mma.sync tf32): g_h = norm_src * (X @ W1) ----------------
// CTA: 128x128 tile, 8 warps (2 row-groups x 4 col-groups), warp tile 64x32.
// BK=32, K=256 -> 8 chunks. A converted to tf32 on load; B pre-converted.
__global__ __launch_bounds__(256) void gemm1_mma_kernel(const float* __restrict__ X, int n) {
    __shared__ uint32_t As[128][36];   // [row][k], pad 36 for conflict-free frag loads
    __shared__ uint32_t Bs[128][36];   // [col][k]

    int t = threadIdx.x;
    int wid = t >> 5;
    int lane = t & 31;
    int row0 = blockIdx.x * 128;

    int wr = wid & 1;                  // row group: rows wr*64 .. +63
    int wc = wid >> 1;                 // col group: cols wc*32 .. +31

    // loader mapping: 2 threads per row, 16 cols each
    int lr = t >> 1;                   // 0..127
    int off = (t & 1) << 4;            // 0 or 16
    int arow = row0 + lr;
    bool avalid = arow < n;
    const float* Xrow = X + (size_t)arow * F_IN;
    const uint32_t* Brow = g_w1t + (size_t)lr * F_IN;

    float acc[4][4][4];                // [m-frag][n-frag][c0..c3]
    #pragma unroll
    for (int f = 0; f < 4; f++)
        #pragma unroll
        for (int g = 0; g < 4; g++)
            #pragma unroll
            for (int q = 0; q < 4; q++) acc[f][g][q] = 0.f;

    int lg = lane >> 2;                // 0..7
    int lk = lane & 3;                 // 0..3

    #pragma unroll 1
    for (int kc = 0; kc < 8; kc++) {
        // load A chunk 128x32 (cvt tf32)
        #pragma unroll
        for (int i = 0; i < 4; i++) {
            float4 v = make_float4(0.f, 0.f, 0.f, 0.f);
            if (avalid) v = *(const float4*)(Xrow + kc * 32 + off + i * 4);
            As[lr][off + i * 4 + 0] = cvt_tf32(v.x);
            As[lr][off + i * 4 + 1] = cvt_tf32(v.y);
            As[lr][off + i * 4 + 2] = cvt_tf32(v.z);
            As[lr][off + i * 4 + 3] = cvt_tf32(v.w);
        }
        // load B chunk 128x32 (pre-converted bits)
        #pragma unroll
        for (int i = 0; i < 4; i++) {
            uint4 u = *(const uint4*)(Brow + kc * 32 + off + i * 4);
            Bs[lr][off + i * 4 + 0] = u.x;
            Bs[lr][off + i * 4 + 1] = u.y;
            Bs[lr][off + i * 4 + 2] = u.z;
            Bs[lr][off + i * 4 + 3] = u.w;
        }
        __syncthreads();

        #pragma unroll
        for (int k8 = 0; k8 < 4; k8++) {
            int kb = k8 * 8;
            uint32_t a[4][4], b[4][2];
            #pragma unroll
            for (int f = 0; f < 4; f++) {
                int r = wr * 64 + f * 16 + lg;
                a[f][0] = As[r][kb + lk];
                a[f][1] = As[r + 8][kb + lk];
                a[f][2] = As[r][kb + lk + 4];
                a[f][3] = As[r + 8][kb + lk + 4];
            }
            #pragma unroll
            for (int g = 0; g < 4; g++) {
                int ccol = wc * 32 + g * 8 + lg;
                b[g][0] = Bs[ccol][kb + lk];
                b[g][1] = Bs[ccol][kb + lk + 4];
            }
            #pragma unroll
            for (int f = 0; f < 4; f++)
                #pragma unroll
                for (int g = 0; g < 4; g++)
                    mma_tf32(acc[f][g], a[f], b[g]);
        }
        __syncthreads();
    }

    // epilogue: scale by norm_src, write g_h
    #pragma unroll
    for (int f = 0; f < 4; f++) {
        int rbase = row0 + wr * 64 + f * 16;
        int r0 = rbase + lg;
        int r1 = r0 + 8;
        float ns0 = (r0 < n) ? g_norm_src[r0] : 0.f;
        float ns1 = (r1 < n) ? g_norm_src[r1] : 0.f;
        #pragma unroll
        for (int g = 0; g < 4; g++) {
            int cc = wc * 32 + g * 8 + 2 * lk;
            if (r0 < n) {
                float2 o = make_float2(acc[f][g][0] * ns0, acc[f][g][1] * ns0);
                *(float2*)(g_h + (size_t)r0 * N_HID + cc) = o;
            }
            if (r1 < n) {
                float2 o = make_float2(acc[f][g][2] * ns1, acc[f][g][3] * ns1);
                *(float2*)(g_h + (size_t)r1 * N_HID + cc) = o;
            }
        }
    }
}

// ---------------- SpMM1: g_agg[dst] += g_h[src] (128 wide) ----------------
__global__ void spmm1_kernel(const int* __restrict__ src, const int* __restrict__ dst, int E) {
    int t = blockIdx.x * blockDim.x + threadIdx.x;
    if (t >= E * 16) return;
    int e = t >> 4;
    int c = t & 15;
    int s = load_idx(src, e);
    int d = load_idx(dst, e);
    const float* hp = g_h + (size_t)s * N_HID + (c << 3);
    float* ap = g_agg + (size_t)d * N_HID + (c << 3);
    float4 v0 = *(const float4*)hp;
    float4 v1 = *(const float4*)(hp + 4);
    atomicAdd((float4*)ap, v0);
    atomicAdd((float4*)(ap + 4), v1);
}

// ---------------- GEMM2: g_h2[n,40] = (relu(agg*nd + b1) * ns) @ W2[128,40] ----------------
__global__ __launch_bounds__(256) void gemm2_kernel(const float* __restrict__ b1,
                                                    const float* __restrict__ W2, int n) {
    __shared__ float As2[16][132];
    __shared__ float Bs2[16][40];
    __shared__ float b1s[N_HID];

    int t = threadIdx.x;
    int row0 = blockIdx.x * 128;

    if (t < N_HID) b1s[t] = b1[t];
    __syncthreads();

    int rowg = t >> 3;
    int colg = t & 7;

    float acc[4][5];
    #pragma unroll
    for (int i = 0; i < 4; i++)
        #pragma unroll
        for (int j = 0; j < 5; j++) acc[i][j] = 0.f;

    for (int k0 = 0; k0 < N_HID; k0 += 16) {
        #pragma unroll
        for (int i = 0; i < 2; i++) {
            int idx = t + i * 256;
            int am = idx >> 2;
            int ak = (idx & 3) << 2;
            int r = row0 + am;
            float4 v = make_float4(0.f, 0.f, 0.f, 0.f);
            float nd = 0.f, ns = 0.f;
            if (r < n) {
                nd = g_norm_dst[r];
                ns = g_norm_src[r];
                v = *(const float4*)(g_agg + (size_t)r * N_HID + k0 + ak);
            }
            As2[ak + 0][am] = fmaxf(fmaf(v.x, nd, b1s[k0 + ak + 0]), 0.f) * ns;
            As2[ak + 1][am] = fmaxf(fmaf(v.y, nd, b1s[k0 + ak + 1]), 0.f) * ns;
            As2[ak + 2][am] = fmaxf(fmaf(v.z, nd, b1s[k0 + ak + 2]), 0.f) * ns;
            As2[ak + 3][am] = fmaxf(fmaf(v.w, nd, b1s[k0 + ak + 3]), 0.f) * ns;
        }
        for (int idx = t; idx < 16 * N_CLS; idx += 256) {
            int bk = idx / N_CLS;
            int bn = idx - bk * N_CLS;
            Bs2[bk][bn] = W2[(size_t)(k0 + bk) * N_CLS + bn];
        }
        __syncthreads();

        #pragma unroll
        for (int k = 0; k < 16; k++) {
            float4 a4 = *(const float4*)&As2[k][rowg << 2];
            float aa[4] = {a4.x, a4.y, a4.z, a4.w};
            #pragma unroll
            for (int j = 0; j < 5; j++) {
                float b = Bs2[k][colg * 5 + j];
                #pragma unroll
                for (int i = 0; i < 4; i++)
                    acc[i][j] = fmaf(aa[i], b, acc[i][j]);
            }
        }
        __syncthreads();
    }

    #pragma unroll
    for (int i = 0; i < 4; i++) {
        int r = row0 + (rowg << 2) + i;
        if (r < n) {
            float* hp = g_h2 + (size_t)r * N_CLS + colg * 5;
            #pragma unroll
            for (int j = 0; j < 5; j++) hp[j] = acc[i][j];
        }
    }
}

// ---------------- SpMM2: out[dst] += g_h2[src] (40 wide) ----------------
__global__ void spmm2_kernel(const int* __restrict__ src, const int* __restrict__ dst,
                             float* __restrict__ out, int E) {
    int t = blockIdx.x * blockDim.x + threadIdx.x;
    if (t >= E * 5) return;
    int e = t / 5;
    int g = t - e * 5;
    int s = load_idx(src, e);
    int d = load_idx(dst, e);
    const float* hp = g_h2 + (size_t)s * N_CLS + (g << 3);
    float* op = out + (size_t)d * N_CLS + (g << 3);
    float4 v0 = *(const float4*)hp;
    float4 v1 = *(const float4*)(hp + 4);
    atomicAdd((float4*)op, v0);
    atomicAdd((float4*)(op + 4), v1);
}

// ---------------- finalize: out = out * norm_dst + b2 ----------------
__global__ void finalize_kernel(float* __restrict__ out, const float* __restrict__ b2, int n) {
    int t = blockIdx.x * blockDim.x + threadIdx.x;
    if (t < n * N_CLS) {
        int r = t / N_CLS;
        int c = t - r * N_CLS;
        out[t] = fmaf(out[t], g_norm_dst[r], b2[c]);
    }
}

// ---------------- launch ----------------
extern "C" void kernel_launch(void* const* d_in, const int* in_sizes, int n_in,
                              void* d_out, int out_size) {
    const float* X  = (const float*)d_in[0];
    const int* src  = (const int*)d_in[1];
    const int* dst  = (const int*)d_in[2];
    const float* W1 = (const float*)d_in[3];
    const float* b1 = (const float*)d_in[4];
    const float* W2 = (const float*)d_in[5];
    const float* b2 = (const float*)d_in[6];
    float* out = (float*)d_out;

    int n = in_sizes[0] / F_IN;   // 100000
    int E = in_sizes[1];          // 800000

    init_kernel<<<2048, 256>>>((float4*)out, src, n, out_size / 4);
    degree_kernel<<<(E + 255) / 256, 256>>>(src, dst, E);
    norm_kernel<<<(n + 255) / 256, 256>>>(n);
    w1t_kernel<<<(N_HID * F_IN + 255) / 256, 256>>>(W1);
    gemm1_mma_kernel<<<(n + 127) / 128, 256>>>(X, n);
    spmm1_kernel<<<(E * 16 + 255) / 256, 256>>>(src, dst, E);
    gemm2_kernel<<<(n + 127) / 128, 256>>>(b1, W2, n);
    spmm2_kernel<<<(E * 5 + 255) / 256, 256>>>(src, dst, out, E);
    finalize_kernel<<<(n * N_CLS + 255) / 256, 256>>>(out, b2, n);
}

// round 6
// speedup vs baseline: 1.0333x; 1.0333x over previous
#include <cuda_runtime.h>
#include <cstdint>

#define N_NODES 100000
#define N_EDGES_MAX 800000
#define F_IN 256
#define N_HID 128
#define N_CLS 40

// ---------------- device scratch (static, no allocations) ----------------
__device__ float g_norm_src[N_NODES];
__device__ float g_norm_dst[N_NODES];
__device__ float g_h[(size_t)N_NODES * N_HID];    // layer-1 projected features
__device__ float g_act[(size_t)N_NODES * N_HID];  // layer-1 activations
__device__ float g_h2[(size_t)N_NODES * N_CLS];   // layer-2 projected features
__device__ uint32_t g_w1t[(size_t)N_HID * F_IN];  // W1^T [n][k], tf32-rounded bits
__device__ int g_indeg[N_NODES];
__device__ int g_outdeg[N_NODES];
__device__ int g_rowptr[N_NODES + 1];
__device__ int g_cursor[N_NODES];
__device__ int g_esrc[N_EDGES_MAX];
__device__ int g_idx64;                            // 1 if src/dst are int64

// ---------------- helpers ----------------
__device__ __forceinline__ int load_idx(const int* p, int e) {
    return g_idx64 ? p[2 * e] : p[e];
}

__device__ __forceinline__ uint32_t cvt_tf32(float f) {
    uint32_t u;
    asm("cvt.rna.tf32.f32 %0, %1;" : "=r"(u) : "f"(f));
    return u;
}

__device__ __forceinline__ void mma_tf32(float* c, const uint32_t* a, const uint32_t* b) {
    asm volatile("mma.sync.aligned.m16n8k8.row.col.f32.tf32.tf32.f32 "
        "{%0,%1,%2,%3}, {%4,%5,%6,%7}, {%8,%9}, {%0,%1,%2,%3};"
        : "+f"(c[0]), "+f"(c[1]), "+f"(c[2]), "+f"(c[3])
        : "r"(a[0]), "r"(a[1]), "r"(a[2]), "r"(a[3]), "r"(b[0]), "r"(b[1]));
}

// ---------------- init: detect index dtype + zero degree counters ----------------
__global__ void init_kernel(const int* __restrict__ src32, int n) {
    int i = blockIdx.x * blockDim.x + threadIdx.x;
    if (i == 0) {
        int is64 = 1;
        #pragma unroll 1
        for (int k = 0; k < 64; k++) {
            if (src32[2 * k + 1] != 0) { is64 = 0; break; }
        }
        g_idx64 = is64;
    }
    if (i < n) { g_indeg[i] = 0; g_outdeg[i] = 0; }
}

// ---------------- hist: degree counts ----------------
__global__ void hist_kernel(const int* __restrict__ src, const int* __restrict__ dst, int E) {
    int i = blockIdx.x * blockDim.x + threadIdx.x;
    if (i < E) {
        atomicAdd(&g_outdeg[load_idx(src, i)], 1);
        atomicAdd(&g_indeg[load_idx(dst, i)], 1);
    }
}

// ---------------- scan: exclusive prefix sum of indeg -> rowptr, cursor ----------------
__global__ void scan_kernel(int n, int E) {
    __shared__ int wsum[32];
    __shared__ int stotal;
    int t = threadIdx.x;
    int lane = t & 31, w = t >> 5;
    int run = 0;
    for (int base = 0; base < n; base += 1024) {
        int i = base + t;
        int x = (i < n) ? g_indeg[i] : 0;
        int v = x;
        #pragma unroll
        for (int o = 1; o < 32; o <<= 1) {
            int y = __shfl_up_sync(0xFFFFFFFFu, v, o);
            if (lane >= o) v += y;
        }
        if (lane == 31) wsum[w] = v;
        __syncthreads();
        if (w == 0) {
            int s = wsum[lane];
            #pragma unroll
            for (int o = 1; o < 32; o <<= 1) {
                int y = __shfl_up_sync(0xFFFFFFFFu, s, o);
                if (lane >= o) s += y;
            }
            wsum[lane] = s;
            if (lane == 31) stotal = s;
        }
        __syncthreads();
        int excl = v - x + (w > 0 ? wsum[w - 1] : 0) + run;
        if (i < n) { g_rowptr[i] = excl; g_cursor[i] = excl; }
        run += stotal;
        __syncthreads();
    }
    if (t == 0) g_rowptr[n] = E;
}

// ---------------- scatter: fill CSR edge-source list ----------------
__global__ void scatter_kernel(const int* __restrict__ src, const int* __restrict__ dst, int E) {
    int i = blockIdx.x * blockDim.x + threadIdx.x;
    if (i < E) {
        int s = load_idx(src, i);
        int d = load_idx(dst, i);
        int pos = atomicAdd(&g_cursor[d], 1);
        g_esrc[pos] = s;
    }
}

// ---------------- norms from integer degrees ----------------
__global__ void norm_kernel(int n) {
    int i = blockIdx.x * blockDim.x + threadIdx.x;
    if (i < n) {
        int od = g_outdeg[i];
        int id = g_indeg[i];
        g_norm_src[i] = (od > 0) ? rsqrtf((float)od) : 0.f;
        g_norm_dst[i] = (id > 0) ? rsqrtf((float)id) : 0.f;
    }
}

// ---------------- W1 transpose + tf32 rounding ----------------
__global__ void w1t_kernel(const float* __restrict__ W1) {
    int i = blockIdx.x * blockDim.x + threadIdx.x;
    if (i < N_HID * F_IN) {
        int nrow = i >> 8;
        int k = i & 255;
        g_w1t[(size_t)nrow * F_IN + k] = cvt_tf32(W1[(size_t)k * N_HID + nrow]);
    }
}

// ---------------- GEMM1 (mma.sync tf32): g_h = norm_src * (X @ W1) ----------------
__global__ __launch_bounds__(256) void gemm1_mma_kernel(const float* __restrict__ X, int n) {
    __shared__ uint32_t As[128][36];
    __shared__ uint32_t Bs[128][36];

    int t = threadIdx.x;
    int wid = t >> 5;
    int lane = t & 31;
    int row0 = blockIdx.x * 128;

    int wr = wid & 1;
    int wc = wid >> 1;

    int lr = t >> 1;
    int off = (t & 1) << 4;
    int arow = row0 + lr;
    bool avalid = arow < n;
    const float* Xrow = X + (size_t)arow * F_IN;
    const uint32_t* Brow = g_w1t + (size_t)lr * F_IN;

    float acc[4][4][4];
    #pragma unroll
    for (int f = 0; f < 4; f++)
        #pragma unroll
        for (int g = 0; g < 4; g++)
            #pragma unroll
            for (int q = 0; q < 4; q++) acc[f][g][q] = 0.f;

    int lg = lane >> 2;
    int lk = lane & 3;

    #pragma unroll 1
    for (int kc = 0; kc < 8; kc++) {
        #pragma unroll
        for (int i = 0; i < 4; i++) {
            float4 v = make_float4(0.f, 0.f, 0.f, 0.f);
            if (avalid) v = *(const float4*)(Xrow + kc * 32 + off + i * 4);
            As[lr][off + i * 4 + 0] = cvt_tf32(v.x);
            As[lr][off + i * 4 + 1] = cvt_tf32(v.y);
            As[lr][off + i * 4 + 2] = cvt_tf32(v.z);
            As[lr][off + i * 4 + 3] = cvt_tf32(v.w);
        }
        #pragma unroll
        for (int i = 0; i < 4; i++) {
            uint4 u = *(const uint4*)(Brow + kc * 32 + off + i * 4);
            Bs[lr][off + i * 4 + 0] = u.x;
            Bs[lr][off + i * 4 + 1] = u.y;
            Bs[lr][off + i * 4 + 2] = u.z;
            Bs[lr][off + i * 4 + 3] = u.w;
        }
        __syncthreads();

        #pragma unroll
        for (int k8 = 0; k8 < 4; k8++) {
            int kb = k8 * 8;
            uint32_t a[4][4], b[4][2];
            #pragma unroll
            for (int f = 0; f < 4; f++) {
                int r = wr * 64 + f * 16 + lg;
                a[f][0] = As[r][kb + lk];
                a[f][1] = As[r + 8][kb + lk];
                a[f][2] = As[r][kb + lk + 4];
                a[f][3] = As[r + 8][kb + lk + 4];
            }
            #pragma unroll
            for (int g = 0; g < 4; g++) {
                int ccol = wc * 32 + g * 8 + lg;
                b[g][0] = Bs[ccol][kb + lk];
                b[g][1] = Bs[ccol][kb + lk + 4];
            }
            #pragma unroll
            for (int f = 0; f < 4; f++)
                #pragma unroll
                for (int g = 0; g < 4; g++)
                    mma_tf32(acc[f][g], a[f], b[g]);
        }
        __syncthreads();
    }

    #pragma unroll
    for (int f = 0; f < 4; f++) {
        int rbase = row0 + wr * 64 + f * 16;
        int r0 = rbase + lg;
        int r1 = r0 + 8;
        float ns0 = (r0 < n) ? g_norm_src[r0] : 0.f;
        float ns1 = (r1 < n) ? g_norm_src[r1] : 0.f;
        #pragma unroll
        for (int g = 0; g < 4; g++) {
            int cc = wc * 32 + g * 8 + 2 * lk;
            if (r0 < n) {
                float2 o = make_float2(acc[f][g][0] * ns0, acc[f][g][1] * ns0);
                *(float2*)(g_h + (size_t)r0 * N_HID + cc) = o;
            }
            if (r1 < n) {
                float2 o = make_float2(acc[f][g][2] * ns1, acc[f][g][3] * ns1);
                *(float2*)(g_h + (size_t)r1 * N_HID + cc) = o;
            }
        }
    }
}

// ---------------- SpMM1 (CSR gather) + activation fused ----------------
// One warp per dst node; each lane owns 4 contiguous cols (float4).
// g_act[d] = relu( (sum_{e in row d} g_h[src_e]) * nd + b1 ) * ns
__global__ __launch_bounds__(256) void spmm1_csr_kernel(const float* __restrict__ b1, int n) {
    __shared__ float b1s[N_HID];
    int t = threadIdx.x;
    int w = t >> 5, lane = t & 31;
    if (t < N_HID) b1s[t] = b1[t];
    __syncthreads();

    int d = blockIdx.x * 8 + w;
    if (d >= n) return;

    int start = g_rowptr[d];
    int end = g_rowptr[d + 1];
    int c = lane << 2;

    float4 acc0 = make_float4(0.f, 0.f, 0.f, 0.f);
    float4 acc1 = make_float4(0.f, 0.f, 0.f, 0.f);

    for (int base = start; base < end; base += 32) {
        int m = end - base;
        int sv = (lane < m) ? g_esrc[base + lane] : 0;
        int cnt = m < 32 ? m : 32;
        int i = 0;
        for (; i + 1 < cnt; i += 2) {
            int s0 = __shfl_sync(0xFFFFFFFFu, sv, i);
            int s1 = __shfl_sync(0xFFFFFFFFu, sv, i + 1);
            float4 v0 = *(const float4*)(g_h + (size_t)s0 * N_HID + c);
            float4 v1 = *(const float4*)(g_h + (size_t)s1 * N_HID + c);
            acc0.x += v0.x; acc0.y += v0.y; acc0.z += v0.z; acc0.w += v0.w;
            acc1.x += v1.x; acc1.y += v1.y; acc1.z += v1.z; acc1.w += v1.w;
        }
        if (i < cnt) {
            int s0 = __shfl_sync(0xFFFFFFFFu, sv, i);
            float4 v0 = *(const float4*)(g_h + (size_t)s0 * N_HID + c);
            acc0.x += v0.x; acc0.y += v0.y; acc0.z += v0.z; acc0.w += v0.w;
        }
    }
    acc0.x += acc1.x; acc0.y += acc1.y; acc0.z += acc1.z; acc0.w += acc1.w;

    float nd = g_norm_dst[d];
    float ns = g_norm_src[d];
    float4 bb = *(const float4*)(b1s + c);
    float4 o;
    o.x = fmaxf(fmaf(acc0.x, nd, bb.x), 0.f) * ns;
    o.y = fmaxf(fmaf(acc0.y, nd, bb.y), 0.f) * ns;
    o.z = fmaxf(fmaf(acc0.z, nd, bb.z), 0.f) * ns;
    o.w = fmaxf(fmaf(acc0.w, nd, bb.w), 0.f) * ns;
    *(float4*)(g_act + (size_t)d * N_HID + c) = o;
}

// ---------------- GEMM2: g_h2[n,40] = g_act @ W2[128,40] ----------------
__global__ __launch_bounds__(256) void gemm2_kernel(const float* __restrict__ W2, int n) {
    __shared__ float As2[16][132];
    __shared__ float Bs2[16][40];

    int t = threadIdx.x;
    int row0 = blockIdx.x * 128;

    int rowg = t >> 3;
    int colg = t & 7;

    float acc[4][5];
    #pragma unroll
    for (int i = 0; i < 4; i++)
        #pragma unroll
        for (int j = 0; j < 5; j++) acc[i][j] = 0.f;

    for (int k0 = 0; k0 < N_HID; k0 += 16) {
        #pragma unroll
        for (int i = 0; i < 2; i++) {
            int idx = t + i * 256;
            int am = idx >> 2;
            int ak = (idx & 3) << 2;
            int r = row0 + am;
            float4 v = make_float4(0.f, 0.f, 0.f, 0.f);
            if (r < n) v = *(const float4*)(g_act + (size_t)r * N_HID + k0 + ak);
            As2[ak + 0][am] = v.x;
            As2[ak + 1][am] = v.y;
            As2[ak + 2][am] = v.z;
            As2[ak + 3][am] = v.w;
        }
        for (int idx = t; idx < 16 * N_CLS; idx += 256) {
            int bk = idx / N_CLS;
            int bn = idx - bk * N_CLS;
            Bs2[bk][bn] = W2[(size_t)(k0 + bk) * N_CLS + bn];
        }
        __syncthreads();

        #pragma unroll
        for (int k = 0; k < 16; k++) {
            float4 a4 = *(const float4*)&As2[k][rowg << 2];
            float aa[4] = {a4.x, a4.y, a4.z, a4.w};
            #pragma unroll
            for (int j = 0; j < 5; j++) {
                float b = Bs2[k][colg * 5 + j];
                #pragma unroll
                for (int i = 0; i < 4; i++)
                    acc[i][j] = fmaf(aa[i], b, acc[i][j]);
            }
        }
        __syncthreads();
    }

    #pragma unroll
    for (int i = 0; i < 4; i++) {
        int r = row0 + (rowg << 2) + i;
        if (r < n) {
            float* hp = g_h2 + (size_t)r * N_CLS + colg * 5;
            #pragma unroll
            for (int j = 0; j < 5; j++) hp[j] = acc[i][j];
        }
    }
}

// ---------------- SpMM2 (CSR gather) + finalize fused ----------------
// One warp per dst node; lane owns col lane and (lane<8) col lane+32.
// out[d] = (sum g_h2[src]) * nd + b2
__global__ __launch_bounds__(256) void spmm2_csr_kernel(const float* __restrict__ b2,
                                                        float* __restrict__ out, int n) {
    __shared__ float b2s[N_CLS];
    int t = threadIdx.x;
    int w = t >> 5, lane = t & 31;
    if (t < N_CLS) b2s[t] = b2[t];
    __syncthreads();

    int d = blockIdx.x * 8 + w;
    if (d >= n) return;

    int start = g_rowptr[d];
    int end = g_rowptr[d + 1];

    float a0 = 0.f, a1 = 0.f;
    for (int base = start; base < end; base += 32) {
        int m = end - base;
        int sv = (lane < m) ? g_esrc[base + lane] : 0;
        int cnt = m < 32 ? m : 32;
        for (int i = 0; i < cnt; i++) {
            int s = __shfl_sync(0xFFFFFFFFu, sv, i);
            const float* hp = g_h2 + (size_t)s * N_CLS;
            a0 += hp[lane];
            if (lane < 8) a1 += hp[32 + lane];
        }
    }

    float nd = g_norm_dst[d];
    float* op = out + (size_t)d * N_CLS;
    op[lane] = fmaf(a0, nd, b2s[lane]);
    if (lane < 8) op[32 + lane] = fmaf(a1, nd, b2s[32 + lane]);
}

// ---------------- launch ----------------
extern "C" void kernel_launch(void* const* d_in, const int* in_sizes, int n_in,
                              void* d_out, int out_size) {
    const float* X  = (const float*)d_in[0];
    const int* src  = (const int*)d_in[1];
    const int* dst  = (const int*)d_in[2];
    const float* W1 = (const float*)d_in[3];
    const float* b1 = (const float*)d_in[4];
    const float* W2 = (const float*)d_in[5];
    const float* b2 = (const float*)d_in[6];
    float* out = (float*)d_out;

    int n = in_sizes[0] / F_IN;   // 100000
    int E = in_sizes[1];          // 800000

    init_kernel<<<(n + 255) / 256, 256>>>(src, n);
    hist_kernel<<<(E + 255) / 256, 256>>>(src, dst, E);
    scan_kernel<<<1, 1024>>>(n, E);
    scatter_kernel<<<(E + 255) / 256, 256>>>(src, dst, E);
    norm_kernel<<<(n + 255) / 256, 256>>>(n);
    w1t_kernel<<<(N_HID * F_IN + 255) / 256, 256>>>(W1);
    gemm1_mma_kernel<<<(n + 127) / 128, 256>>>(X, n);
    spmm1_csr_kernel<<<(n + 7) / 8, 256>>>(b1, n);
    gemm2_kernel<<<(n + 127) / 128, 256>>>(W2, n);
    spmm2_csr_kernel<<<(n + 7) / 8, 256>>>(b2, out, n);
}